// round 8
// baseline (speedup 1.0000x reference)
#include <cuda_runtime.h>
#include <cuda_bf16.h>
#include <math.h>
#include <stdint.h>

#define NROWS 65536
#define DIMS  64
#define KCODE 1024
#define BM    128
#define THREADS 256
#define NCHUNK 32           // 32 chunks of 32 codes
#define CHW    32
#define NBLK   (NROWS/BM)   // 512 row-blocks
#define GRID   296          // 148 SMs x occ 2; work-stealing over NBLK

// output layout (floats): [loss(1) | quantized(4194304) | perplexity(1) | encodings(67108864)]
#define Q_OFF    1
#define Q_SIZE   4194304
#define P_OFF    (Q_OFF + Q_SIZE)
#define ENC_OFF  (P_OFF + 1)

#define LDB   72            // padded bf16 row: 144B (conflict-free ldmatrix)
#define LDBB  144
#define IMGB  (KCODE * LDBB)

// smem byte offsets
#define A_OFF    0                    // 3 images x 128 x 144 = 55296
#define B_OFF    55296                // 2 bufs x 13824
#define BCHUNKB  13824
#define E2_OFF   82944                // 1024 f32
#define X2_OFF   87040                // 128 f32
#define RMIN_OFF 87552
#define RIDX_OFF 88064
#define BLK_OFF  88576
#define SMEM_BYTES 88704

__device__ __nv_bfloat16 g_cbs[3 * KCODE * LDB];  // 3 padded split images
__device__ float  g_e2[KCODE];
__device__ int    g_counts[KCODE];   // zero at load; finalize re-zeroes
__device__ double g_loss_sum;
__device__ int    g_blk;             // work-steal counter; finalize re-zeroes

__device__ __forceinline__ uint32_t smem_u32(const void* p) {
    uint32_t a;
    asm("{ .reg .u64 t; cvta.to.shared.u64 t, %1; cvt.u32.u64 %0, t; }" : "=r"(a) : "l"(p));
    return a;
}
#define LDSM_X4(r0, r1, r2, r3, addr) \
    asm volatile("ldmatrix.sync.aligned.m8n8.x4.shared.b16 {%0,%1,%2,%3}, [%4];" \
                 : "=r"(r0), "=r"(r1), "=r"(r2), "=r"(r3) : "r"(addr))
#define MMA_BF16(c0, c1, c2, c3, a0, a1, a2, a3, b0, b1) \
    asm volatile("mma.sync.aligned.m16n8k16.row.col.f32.bf16.bf16.f32 " \
                 "{%0,%1,%2,%3}, {%4,%5,%6,%7}, {%8,%9}, {%0,%1,%2,%3};" \
                 : "+f"(c0), "+f"(c1), "+f"(c2), "+f"(c3) \
                 : "r"(a0), "r"(a1), "r"(a2), "r"(a3), "r"(b0), "r"(b1))
#define CPA16(dst, src) \
    asm volatile("cp.async.cg.shared.global [%0], [%1], 16;" \
                 :: "r"((uint32_t)(dst)), "l"((unsigned long long)(src)) : "memory")
#define CPA_COMMIT() asm volatile("cp.async.commit_group;" ::: "memory")
#define CPA_WAIT0()  asm volatile("cp.async.wait_group 0;" ::: "memory")

// ---------------- prologue: split codebook into 3 padded bf16 images + e2 ----------------
__global__ void vq_prep_kernel(const float* __restrict__ cb) {
    int k = blockIdx.x * 128 + threadIdx.x;
    float e2 = 0.f;
    for (int c = 0; c < DIMS; c++) {
        float v = cb[k * DIMS + c];
        e2 = fmaf(v, v, e2);
        __nv_bfloat16 h = __float2bfloat16(v);
        float r1 = v - __bfloat162float(h);
        __nv_bfloat16 m = __float2bfloat16(r1);
        float r2 = r1 - __bfloat162float(m);
        __nv_bfloat16 l = __float2bfloat16(r2);
        g_cbs[0 * KCODE * LDB + k * LDB + c] = h;
        g_cbs[1 * KCODE * LDB + k * LDB + c] = m;
        g_cbs[2 * KCODE * LDB + k * LDB + c] = l;
    }
    g_e2[k] = e2;
}

// ---------------- main fused persistent kernel ----------------
__global__ __launch_bounds__(THREADS, 2)
void vq_main_kernel(const float* __restrict__ x,
                    const float* __restrict__ cb,
                    float* __restrict__ out) {
    extern __shared__ char smem[];
    const uint32_t su = smem_u32(smem);
    float* e2s  = (float*)(smem + E2_OFF);
    float* x2s  = (float*)(smem + X2_OFF);
    float* rmin = (float*)(smem + RMIN_OFF);
    int*   ridx = (int*)(smem + RIDX_OFF);
    int*   sblk = (int*)(smem + BLK_OFF);

    const int tid  = threadIdx.x;
    const int wid  = tid >> 5;
    const int lane = tid & 31;

    #pragma unroll
    for (int i = tid; i < KCODE; i += THREADS) e2s[i] = g_e2[i];

    // cp.async slot map (864 x 16B lines/chunk; 3 slots all threads, 4th iff tid<96)
    const unsigned long long gb = (unsigned long long)__cvta_generic_to_global(g_cbs);
    unsigned long long cpa_src[4];
    uint32_t cpa_dst[4];
    const bool has4 = (tid < 96);
    #pragma unroll
    for (int u = 0; u < 4; u++) {
        int i = tid + u * 256;
        int q = i / 288, r = i % 288;
        cpa_dst[u] = (uint32_t)(q * 4608 + r * 16);
        cpa_src[u] = gb + (unsigned long long)q * IMGB + (unsigned long long)r * 16;
    }

    // B x4 lane offset: mats {ks_lo:16B0, ks_lo:16B1, ks_hi:16B0, ks_hi:16B1}
    const int bofs4 = (lane & 7) * LDBB + ((lane >> 3) & 1) * 16 + (lane >> 4) * 32;
    const int r0 = wid * 16 + (lane >> 2);
    const int r1 = r0 + 8;

    while (true) {
        __syncthreads();
        if (tid == 0) *sblk = atomicAdd(&g_blk, 1);
        __syncthreads();
        const int blk = *sblk;
        if (blk >= NBLK) break;

        const int n0  = blk * BM;
        const int b   = n0 >> 10;
        const int hw0 = n0 & 1023;
        const float* xb = x + (size_t)b * 65536 + hw0;

        // prefetch B chunk 0
        {
            uint32_t d0 = su + B_OFF;
            CPA16(d0 + cpa_dst[0], cpa_src[0]);
            CPA16(d0 + cpa_dst[1], cpa_src[1]);
            CPA16(d0 + cpa_dst[2], cpa_src[2]);
            if (has4) CPA16(d0 + cpa_dst[3], cpa_src[3]);
            CPA_COMMIT();
        }

        // A setup: 3-way bf16 split, one row per thread
        if (tid < BM) {
            int r = tid;
            float x2 = 0.f;
            #pragma unroll 8
            for (int c = 0; c < DIMS; c++) {
                float v = xb[c * 1024 + r];
                x2 = fmaf(v, v, x2);
                __nv_bfloat16 h = __float2bfloat16(v);
                float rr1 = v - __bfloat162float(h);
                __nv_bfloat16 m = __float2bfloat16(rr1);
                float rr2 = rr1 - __bfloat162float(m);
                __nv_bfloat16 l = __float2bfloat16(rr2);
                *(__nv_bfloat16*)(smem + A_OFF + 0 * 18432 + r * LDBB + c * 2) = h;
                *(__nv_bfloat16*)(smem + A_OFF + 1 * 18432 + r * LDBB + c * 2) = m;
                *(__nv_bfloat16*)(smem + A_OFF + 2 * 18432 + r * LDBB + c * 2) = l;
            }
            x2s[r] = x2;
        }
        __syncthreads();

        // A fragments: 3 images x 4 k-steps
        uint32_t af[3][4][4];
        {
            int row = wid * 16 + (lane & 15);
            int kh  = (lane >> 4) & 1;
            #pragma unroll
            for (int q = 0; q < 3; q++)
                #pragma unroll
                for (int ks = 0; ks < 4; ks++) {
                    uint32_t a = su + A_OFF + q * 18432 + row * LDBB + ks * 32 + kh * 16;
                    LDSM_X4(af[q][ks][0], af[q][ks][1], af[q][ks][2], af[q][ks][3], a);
                }
        }

        const float x2_0 = x2s[r0], x2_1 = x2s[r1];
        float best0 = 3.4e38f, best1 = 3.4e38f;
        int   bidx0 = 0,       bidx1 = 0;

        float* encb = out + ENC_OFF + (size_t)n0 * KCODE;
        float4* enc4 = (float4*)(encb + 2);
        if (tid == 0) *(float2*)encb = make_float2(0.f, 0.f);
        if (tid == 1) *(float2*)(encb + (size_t)BM * KCODE - 2) = make_float2(0.f, 0.f);

        for (int nt = 0; nt < NCHUNK; nt++) {
            CPA_WAIT0();
            __syncthreads();
            if (nt + 1 < NCHUNK) {
                uint32_t d0 = su + B_OFF + ((nt + 1) & 1) * BCHUNKB;
                unsigned long long so = (unsigned long long)(nt + 1) * 4608;
                CPA16(d0 + cpa_dst[0], cpa_src[0] + so);
                CPA16(d0 + cpa_dst[1], cpa_src[1] + so);
                CPA16(d0 + cpa_dst[2], cpa_src[2] + so);
                if (has4) CPA16(d0 + cpa_dst[3], cpa_src[3] + so);
                CPA_COMMIT();
            }
            const uint32_t bufo = su + B_OFF + (nt & 1) * BCHUNKB;

            // 8 independent accumulator chains: accA (hh,mh,lh), accB (hm,hl,mm)
            float accA[4][4], accB[4][4];
            #pragma unroll
            for (int t = 0; t < 4; t++)
                #pragma unroll
                for (int j = 0; j < 4; j++) { accA[t][j] = 0.f; accB[t][j] = 0.f; }

            #pragma unroll
            for (int kp = 0; kp < 2; kp++) {        // ks pairs {0,1}, {2,3}
                const int k0 = kp * 2, k1 = kp * 2 + 1;
                #pragma unroll
                for (int t = 0; t < 4; t++) {
                    uint32_t bb[3][4];
                    #pragma unroll
                    for (int q = 0; q < 3; q++)
                        LDSM_X4(bb[q][0], bb[q][1], bb[q][2], bb[q][3],
                                bufo + q * 4608 + t * 8 * LDBB + kp * 64 + bofs4);
                    // ks lo (regs 0,1): alternate A/B chains, dep spacing 2
                    MMA_BF16(accA[t][0],accA[t][1],accA[t][2],accA[t][3],
                             af[0][k0][0],af[0][k0][1],af[0][k0][2],af[0][k0][3],
                             bb[0][0],bb[0][1]);                               // hh
                    MMA_BF16(accB[t][0],accB[t][1],accB[t][2],accB[t][3],
                             af[0][k0][0],af[0][k0][1],af[0][k0][2],af[0][k0][3],
                             bb[1][0],bb[1][1]);                               // hm
                    MMA_BF16(accA[t][0],accA[t][1],accA[t][2],accA[t][3],
                             af[1][k0][0],af[1][k0][1],af[1][k0][2],af[1][k0][3],
                             bb[0][0],bb[0][1]);                               // mh
                    MMA_BF16(accB[t][0],accB[t][1],accB[t][2],accB[t][3],
                             af[0][k0][0],af[0][k0][1],af[0][k0][2],af[0][k0][3],
                             bb[2][0],bb[2][1]);                               // hl
                    MMA_BF16(accA[t][0],accA[t][1],accA[t][2],accA[t][3],
                             af[2][k0][0],af[2][k0][1],af[2][k0][2],af[2][k0][3],
                             bb[0][0],bb[0][1]);                               // lh
                    MMA_BF16(accB[t][0],accB[t][1],accB[t][2],accB[t][3],
                             af[1][k0][0],af[1][k0][1],af[1][k0][2],af[1][k0][3],
                             bb[1][0],bb[1][1]);                               // mm
                    // ks hi (regs 2,3)
                    MMA_BF16(accA[t][0],accA[t][1],accA[t][2],accA[t][3],
                             af[0][k1][0],af[0][k1][1],af[0][k1][2],af[0][k1][3],
                             bb[0][2],bb[0][3]);
                    MMA_BF16(accB[t][0],accB[t][1],accB[t][2],accB[t][3],
                             af[0][k1][0],af[0][k1][1],af[0][k1][2],af[0][k1][3],
                             bb[1][2],bb[1][3]);
                    MMA_BF16(accA[t][0],accA[t][1],accA[t][2],accA[t][3],
                             af[1][k1][0],af[1][k1][1],af[1][k1][2],af[1][k1][3],
                             bb[0][2],bb[0][3]);
                    MMA_BF16(accB[t][0],accB[t][1],accB[t][2],accB[t][3],
                             af[0][k1][0],af[0][k1][1],af[0][k1][2],af[0][k1][3],
                             bb[2][2],bb[2][3]);
                    MMA_BF16(accA[t][0],accA[t][1],accA[t][2],accA[t][3],
                             af[2][k1][0],af[2][k1][1],af[2][k1][2],af[2][k1][3],
                             bb[0][2],bb[0][3]);
                    MMA_BF16(accB[t][0],accB[t][1],accB[t][2],accB[t][3],
                             af[1][k1][0],af[1][k1][1],af[1][k1][2],af[1][k1][3],
                             bb[1][2],bb[1][3]);
                }
            }

            // fused distance + argmin (ascending order, strict <)
            #pragma unroll
            for (int t = 0; t < 4; t++) {
                int c0 = nt * CHW + t * 8 + (lane & 3) * 2;
                float e2a = e2s[c0], e2b = e2s[c0 + 1];
                float d;
                d = fmaf(-2.f, accA[t][0] + accB[t][0], x2_0) + e2a;
                if (d < best0) { best0 = d; bidx0 = c0; }
                d = fmaf(-2.f, accA[t][1] + accB[t][1], x2_0) + e2b;
                if (d < best0) { best0 = d; bidx0 = c0 + 1; }
                d = fmaf(-2.f, accA[t][2] + accB[t][2], x2_1) + e2a;
                if (d < best1) { best1 = d; bidx1 = c0; }
                d = fmaf(-2.f, accA[t][3] + accB[t][3], x2_1) + e2b;
                if (d < best1) { best1 = d; bidx1 = c0 + 1; }
            }

            // interleaved encodings zero-fill
            #pragma unroll
            for (int u = 0; u < 4; u++) {
                int i = nt * 1024 + u * 256 + tid;
                if (i < 32767) enc4[i] = make_float4(0.f, 0.f, 0.f, 0.f);
            }
        }

        // cross-lane argmin reduce (4 lanes per row), idx tie-break
        #pragma unroll
        for (int off = 1; off < 4; off <<= 1) {
            float ob0 = __shfl_xor_sync(0xffffffffu, best0, off);
            int   oi0 = __shfl_xor_sync(0xffffffffu, bidx0, off);
            if (ob0 < best0 || (ob0 == best0 && oi0 < bidx0)) { best0 = ob0; bidx0 = oi0; }
            float ob1 = __shfl_xor_sync(0xffffffffu, best1, off);
            int   oi1 = __shfl_xor_sync(0xffffffffu, bidx1, off);
            if (ob1 < best1 || (ob1 == best1 && oi1 < bidx1)) { best1 = ob1; bidx1 = oi1; }
        }
        if ((lane & 3) == 0) {
            rmin[r0] = best0; ridx[r0] = bidx0;
            rmin[r1] = best1; ridx[r1] = bidx1;
        }
        __syncthreads();

        if (tid < BM) atomicAdd(&g_counts[ridx[tid]], 1);

        if (tid < 32) {
            double s = (double)rmin[tid] + (double)rmin[tid + 32]
                     + (double)rmin[tid + 64] + (double)rmin[tid + 96];
            #pragma unroll
            for (int o = 16; o > 0; o >>= 1)
                s += __shfl_down_sync(0xffffffffu, s, o);
            if (tid == 0) atomicAdd(&g_loss_sum, s);
        }

        // quantized output (NCHW), coalesced over r
        float* qout = out + Q_OFF;
        #pragma unroll
        for (int i = 0; i < (BM * DIMS) / THREADS; i++) {
            int idx = tid + i * THREADS;
            int c = idx >> 7;
            int r = idx & 127;
            qout[(size_t)b * 65536 + (size_t)c * 1024 + hw0 + r] =
                cb[(size_t)ridx[r] * DIMS + c];
        }

        if (tid < BM)
            encb[(size_t)tid * KCODE + ridx[tid]] = 1.0f;
    }
}

__global__ void vq_finalize_kernel(float* __restrict__ out) {
    __shared__ float red[8];
    int t = threadIdx.x;
    float acc = 0.f;
    #pragma unroll
    for (int i = 0; i < 4; i++) {
        int k = t + i * 256;
        int c = g_counts[k];
        g_counts[k] = 0;
        float p = (float)c * (1.f / 65536.f);
        acc += p * logf(p + 1e-10f);
    }
    #pragma unroll
    for (int o = 16; o > 0; o >>= 1)
        acc += __shfl_down_sync(0xffffffffu, acc, o);
    if ((t & 31) == 0) red[t >> 5] = acc;
    __syncthreads();
    if (t == 0) {
        float s = 0.f;
        #pragma unroll
        for (int w = 0; w < 8; w++) s += red[w];
        out[P_OFF] = expf(-s);
        out[0]     = (float)(1.25 * g_loss_sum / 4194304.0);
        g_loss_sum = 0.0;
        g_blk      = 0;
    }
}

__global__ void vq_nop_kernel() {}

extern "C" void kernel_launch(void* const* d_in, const int* in_sizes, int n_in,
                              void* d_out, int out_size) {
    const float* x  = (const float*)d_in[0];
    const float* cb = (const float*)d_in[1];
    float* out = (float*)d_out;

    cudaFuncSetAttribute(vq_main_kernel,
                         cudaFuncAttributeMaxDynamicSharedMemorySize, SMEM_BYTES);

    vq_prep_kernel<<<8, 128>>>(cb);
    vq_nop_kernel<<<1, 32>>>();
    vq_nop_kernel<<<1, 32>>>();
    vq_main_kernel<<<GRID, THREADS, SMEM_BYTES>>>(x, cb, out);
    vq_finalize_kernel<<<1, 256>>>(out);
}

// round 9
// speedup vs baseline: 1.5794x; 1.5794x over previous
#include <cuda_runtime.h>
#include <cuda_fp16.h>
#include <math.h>
#include <stdint.h>

#define NROWS 65536
#define DIMS  64
#define KCODE 1024
#define BM    128
#define THREADS 256
#define NCHUNK 32           // 32 chunks of 32 codes
#define CHW    32
#define NBLK   (NROWS/BM)   // 512 row-blocks
#define GRID   296          // 148 SMs x occ 2; work-stealing

// output layout (floats): [loss(1) | quantized(4194304) | perplexity(1) | encodings(67108864)]
#define Q_OFF    1
#define Q_SIZE   4194304
#define P_OFF    (Q_OFF + Q_SIZE)
#define ENC_OFF  (P_OFF + 1)

#define LDB   72            // padded fp16 row: 144B (conflict-free ldmatrix)
#define LDBB  144
#define IMGB  (KCODE * LDBB)
#define ESC   256.0f        // codebook pre-scale (exact power of 2)
#define NEG2S (-2.0f/256.0f)

// smem byte offsets
#define A_OFF    0                    // 2 images x 128 x 144 = 36864
#define B_OFF    36864                // 2 bufs x 9216
#define BCHUNKB  9216
#define E2_OFF   55296                // 1024 f32
#define X2_OFF   59392                // 128 f32
#define RMIN_OFF 59904
#define RIDX_OFF 60416
#define BLK_OFF  60928
#define SMEM_BYTES 61056

__device__ __half g_cbs[2 * KCODE * LDB];  // 2 padded split images (scaled by 256)
__device__ float  g_e2[KCODE];
__device__ int    g_counts[KCODE];   // zero at load; finalize re-zeroes
__device__ double g_loss_sum;
__device__ int    g_blk;             // work-steal counter; finalize re-zeroes

__device__ __forceinline__ uint32_t smem_u32(const void* p) {
    uint32_t a;
    asm("{ .reg .u64 t; cvta.to.shared.u64 t, %1; cvt.u32.u64 %0, t; }" : "=r"(a) : "l"(p));
    return a;
}
#define LDSM_X4(r0, r1, r2, r3, addr) \
    asm volatile("ldmatrix.sync.aligned.m8n8.x4.shared.b16 {%0,%1,%2,%3}, [%4];" \
                 : "=r"(r0), "=r"(r1), "=r"(r2), "=r"(r3) : "r"(addr))
#define MMA_F16(c0, c1, c2, c3, a0, a1, a2, a3, b0, b1) \
    asm volatile("mma.sync.aligned.m16n8k16.row.col.f32.f16.f16.f32 " \
                 "{%0,%1,%2,%3}, {%4,%5,%6,%7}, {%8,%9}, {%0,%1,%2,%3};" \
                 : "+f"(c0), "+f"(c1), "+f"(c2), "+f"(c3) \
                 : "r"(a0), "r"(a1), "r"(a2), "r"(a3), "r"(b0), "r"(b1))
#define CPA16(dst, src) \
    asm volatile("cp.async.cg.shared.global [%0], [%1], 16;" \
                 :: "r"((uint32_t)(dst)), "l"((unsigned long long)(src)) : "memory")
#define CPA_COMMIT() asm volatile("cp.async.commit_group;" ::: "memory")
#define CPA_WAIT0()  asm volatile("cp.async.wait_group 0;" ::: "memory")

// ---------------- prologue: split 256*codebook into 2 padded fp16 images + e2 ----------------
__global__ void vq_prep_kernel(const float* __restrict__ cb) {
    int k = blockIdx.x * 128 + threadIdx.x;
    float e2 = 0.f;
    for (int c = 0; c < DIMS; c++) {
        float v = cb[k * DIMS + c];
        e2 = fmaf(v, v, e2);
        float vs = v * ESC;
        __half h = __float2half_rn(vs);
        float r1 = vs - __half2float(h);
        __half l = __float2half_rn(r1);
        g_cbs[0 * KCODE * LDB + k * LDB + c] = h;
        g_cbs[1 * KCODE * LDB + k * LDB + c] = l;
    }
    g_e2[k] = e2;
}

// ---------------- main fused persistent kernel ----------------
__global__ __launch_bounds__(THREADS, 2)
void vq_main_kernel(const float* __restrict__ x,
                    const float* __restrict__ cb,
                    float* __restrict__ out) {
    extern __shared__ char smem[];
    const uint32_t su = smem_u32(smem);
    float* e2s  = (float*)(smem + E2_OFF);
    float* x2s  = (float*)(smem + X2_OFF);
    float* rmin = (float*)(smem + RMIN_OFF);
    int*   ridx = (int*)(smem + RIDX_OFF);
    int*   sblk = (int*)(smem + BLK_OFF);

    const int tid  = threadIdx.x;
    const int wid  = tid >> 5;
    const int lane = tid & 31;

    #pragma unroll
    for (int i = tid; i < KCODE; i += THREADS) e2s[i] = g_e2[i];

    // cp.async slot map: 576 x 16B lines/chunk; slots 0,1 all threads, slot 2 iff tid<64
    const unsigned long long gb = (unsigned long long)__cvta_generic_to_global(g_cbs);
    unsigned long long cpa_src[3];
    uint32_t cpa_dst[3];
    const bool has3 = (tid < 64);
    #pragma unroll
    for (int u = 0; u < 3; u++) {
        int i = tid + u * 256;
        int q = i / 288, r = i % 288;
        cpa_dst[u] = (uint32_t)(q * 4608 + r * 16);
        cpa_src[u] = gb + (unsigned long long)q * IMGB + (unsigned long long)r * 16;
    }

    // B x4 lane offset: mats {ks_lo:16B0, ks_lo:16B1, ks_hi:16B0, ks_hi:16B1}
    const int bofs4 = (lane & 7) * LDBB + ((lane >> 3) & 1) * 16 + (lane >> 4) * 32;
    const int r0 = wid * 16 + (lane >> 2);
    const int r1 = r0 + 8;

    while (true) {
        __syncthreads();
        if (tid == 0) *sblk = atomicAdd(&g_blk, 1);
        __syncthreads();
        const int blk = *sblk;
        if (blk >= NBLK) break;

        const int n0  = blk * BM;
        const int b   = n0 >> 10;
        const int hw0 = n0 & 1023;
        const float* xb = x + (size_t)b * 65536 + hw0;

        // prefetch B chunk 0
        {
            uint32_t d0 = su + B_OFF;
            CPA16(d0 + cpa_dst[0], cpa_src[0]);
            CPA16(d0 + cpa_dst[1], cpa_src[1]);
            if (has3) CPA16(d0 + cpa_dst[2], cpa_src[2]);
            CPA_COMMIT();
        }

        // A setup: 2-way fp16 split, one row per thread
        if (tid < BM) {
            int r = tid;
            float x2 = 0.f;
            #pragma unroll 8
            for (int c = 0; c < DIMS; c++) {
                float v = xb[c * 1024 + r];
                x2 = fmaf(v, v, x2);
                __half h = __float2half_rn(v);
                float rr1 = v - __half2float(h);
                __half l = __float2half_rn(rr1);
                *(__half*)(smem + A_OFF + 0 * 18432 + r * LDBB + c * 2) = h;
                *(__half*)(smem + A_OFF + 1 * 18432 + r * LDBB + c * 2) = l;
            }
            x2s[r] = x2;
        }
        __syncthreads();

        // A fragments: 2 images x 4 k-steps
        uint32_t af[2][4][4];
        {
            int row = wid * 16 + (lane & 15);
            int kh  = (lane >> 4) & 1;
            #pragma unroll
            for (int q = 0; q < 2; q++)
                #pragma unroll
                for (int ks = 0; ks < 4; ks++) {
                    uint32_t a = su + A_OFF + q * 18432 + row * LDBB + ks * 32 + kh * 16;
                    LDSM_X4(af[q][ks][0], af[q][ks][1], af[q][ks][2], af[q][ks][3], a);
                }
        }

        const float x2_0 = x2s[r0], x2_1 = x2s[r1];
        float best0 = 3.4e38f, best1 = 3.4e38f;
        int   bidx0 = 0,       bidx1 = 0;

        float* encb = out + ENC_OFF + (size_t)n0 * KCODE;
        float4* enc4 = (float4*)(encb + 2);
        if (tid == 0) *(float2*)encb = make_float2(0.f, 0.f);
        if (tid == 1) *(float2*)(encb + (size_t)BM * KCODE - 2) = make_float2(0.f, 0.f);

        for (int nt = 0; nt < NCHUNK; nt++) {
            CPA_WAIT0();
            __syncthreads();
            if (nt + 1 < NCHUNK) {
                uint32_t d0 = su + B_OFF + ((nt + 1) & 1) * BCHUNKB;
                unsigned long long so = (unsigned long long)(nt + 1) * 4608;
                CPA16(d0 + cpa_dst[0], cpa_src[0] + so);
                CPA16(d0 + cpa_dst[1], cpa_src[1] + so);
                if (has3) CPA16(d0 + cpa_dst[2], cpa_src[2] + so);
                CPA_COMMIT();
            }
            const uint32_t bufo = su + B_OFF + (nt & 1) * BCHUNKB;

            float acc[4][4];
            #pragma unroll
            for (int t = 0; t < 4; t++)
                #pragma unroll
                for (int j = 0; j < 4; j++) acc[t][j] = 0.f;

            #pragma unroll
            for (int kp = 0; kp < 2; kp++) {        // ks pairs {0,1}, {2,3}
                const int k0 = kp * 2, k1 = kp * 2 + 1;
                #pragma unroll
                for (int t = 0; t < 4; t++) {
                    uint32_t bh[4], bl[4];
                    LDSM_X4(bh[0], bh[1], bh[2], bh[3],
                            bufo + 0 * 4608 + t * 8 * LDBB + kp * 64 + bofs4);
                    LDSM_X4(bl[0], bl[1], bl[2], bl[3],
                            bufo + 1 * 4608 + t * 8 * LDBB + kp * 64 + bofs4);
                    // ks lo: hh, hl, lh
                    MMA_F16(acc[t][0],acc[t][1],acc[t][2],acc[t][3],
                            af[0][k0][0],af[0][k0][1],af[0][k0][2],af[0][k0][3],
                            bh[0],bh[1]);
                    MMA_F16(acc[t][0],acc[t][1],acc[t][2],acc[t][3],
                            af[0][k0][0],af[0][k0][1],af[0][k0][2],af[0][k0][3],
                            bl[0],bl[1]);
                    MMA_F16(acc[t][0],acc[t][1],acc[t][2],acc[t][3],
                            af[1][k0][0],af[1][k0][1],af[1][k0][2],af[1][k0][3],
                            bh[0],bh[1]);
                    // ks hi
                    MMA_F16(acc[t][0],acc[t][1],acc[t][2],acc[t][3],
                            af[0][k1][0],af[0][k1][1],af[0][k1][2],af[0][k1][3],
                            bh[2],bh[3]);
                    MMA_F16(acc[t][0],acc[t][1],acc[t][2],acc[t][3],
                            af[0][k1][0],af[0][k1][1],af[0][k1][2],af[0][k1][3],
                            bl[2],bl[3]);
                    MMA_F16(acc[t][0],acc[t][1],acc[t][2],acc[t][3],
                            af[1][k1][0],af[1][k1][1],af[1][k1][2],af[1][k1][3],
                            bh[2],bh[3]);
                }
            }

            // fused distance + argmin (ascending order, strict <); dot = acc/256
            #pragma unroll
            for (int t = 0; t < 4; t++) {
                int c0 = nt * CHW + t * 8 + (lane & 3) * 2;
                float e2a = e2s[c0], e2b = e2s[c0 + 1];
                float d;
                d = fmaf(NEG2S, acc[t][0], x2_0) + e2a;
                if (d < best0) { best0 = d; bidx0 = c0; }
                d = fmaf(NEG2S, acc[t][1], x2_0) + e2b;
                if (d < best0) { best0 = d; bidx0 = c0 + 1; }
                d = fmaf(NEG2S, acc[t][2], x2_1) + e2a;
                if (d < best1) { best1 = d; bidx1 = c0; }
                d = fmaf(NEG2S, acc[t][3], x2_1) + e2b;
                if (d < best1) { best1 = d; bidx1 = c0 + 1; }
            }

            // interleaved encodings zero-fill
            #pragma unroll
            for (int u = 0; u < 4; u++) {
                int i = nt * 1024 + u * 256 + tid;
                if (i < 32767) enc4[i] = make_float4(0.f, 0.f, 0.f, 0.f);
            }
        }

        // cross-lane argmin reduce (4 lanes per row), idx tie-break
        #pragma unroll
        for (int off = 1; off < 4; off <<= 1) {
            float ob0 = __shfl_xor_sync(0xffffffffu, best0, off);
            int   oi0 = __shfl_xor_sync(0xffffffffu, bidx0, off);
            if (ob0 < best0 || (ob0 == best0 && oi0 < bidx0)) { best0 = ob0; bidx0 = oi0; }
            float ob1 = __shfl_xor_sync(0xffffffffu, best1, off);
            int   oi1 = __shfl_xor_sync(0xffffffffu, bidx1, off);
            if (ob1 < best1 || (ob1 == best1 && oi1 < bidx1)) { best1 = ob1; bidx1 = oi1; }
        }
        if ((lane & 3) == 0) {
            rmin[r0] = best0; ridx[r0] = bidx0;
            rmin[r1] = best1; ridx[r1] = bidx1;
        }
        __syncthreads();

        if (tid < BM) atomicAdd(&g_counts[ridx[tid]], 1);

        if (tid < 32) {
            double s = (double)rmin[tid] + (double)rmin[tid + 32]
                     + (double)rmin[tid + 64] + (double)rmin[tid + 96];
            #pragma unroll
            for (int o = 16; o > 0; o >>= 1)
                s += __shfl_down_sync(0xffffffffu, s, o);
            if (tid == 0) atomicAdd(&g_loss_sum, s);
        }

        // quantized output (NCHW), coalesced over r
        float* qout = out + Q_OFF;
        #pragma unroll
        for (int i = 0; i < (BM * DIMS) / THREADS; i++) {
            int idx = tid + i * THREADS;
            int c = idx >> 7;
            int r = idx & 127;
            qout[(size_t)b * 65536 + (size_t)c * 1024 + hw0 + r] =
                cb[(size_t)ridx[r] * DIMS + c];
        }

        if (tid < BM)
            encb[(size_t)tid * KCODE + ridx[tid]] = 1.0f;
    }
}

__global__ void vq_finalize_kernel(float* __restrict__ out) {
    __shared__ float red[8];
    int t = threadIdx.x;
    float acc = 0.f;
    #pragma unroll
    for (int i = 0; i < 4; i++) {
        int k = t + i * 256;
        int c = g_counts[k];
        g_counts[k] = 0;
        float p = (float)c * (1.f / 65536.f);
        acc += p * logf(p + 1e-10f);
    }
    #pragma unroll
    for (int o = 16; o > 0; o >>= 1)
        acc += __shfl_down_sync(0xffffffffu, acc, o);
    if ((t & 31) == 0) red[t >> 5] = acc;
    __syncthreads();
    if (t == 0) {
        float s = 0.f;
        #pragma unroll
        for (int w = 0; w < 8; w++) s += red[w];
        out[P_OFF] = expf(-s);
        out[0]     = (float)(1.25 * g_loss_sum / 4194304.0);
        g_loss_sum = 0.0;
        g_blk      = 0;
    }
}

__global__ void vq_nop_kernel() {}

extern "C" void kernel_launch(void* const* d_in, const int* in_sizes, int n_in,
                              void* d_out, int out_size) {
    const float* x  = (const float*)d_in[0];
    const float* cb = (const float*)d_in[1];
    float* out = (float*)d_out;

    cudaFuncSetAttribute(vq_main_kernel,
                         cudaFuncAttributeMaxDynamicSharedMemorySize, SMEM_BYTES);

    vq_prep_kernel<<<8, 128>>>(cb);
    vq_nop_kernel<<<1, 32>>>();
    vq_nop_kernel<<<1, 32>>>();
    vq_main_kernel<<<GRID, THREADS, SMEM_BYTES>>>(x, cb, out);
    vq_finalize_kernel<<<1, 256>>>(out);
}